// round 13
// baseline (speedup 1.0000x reference)
#include <cuda_runtime.h>
#include <cuda_bf16.h>
#include <cstdint>

// LIF spiking scan:  x[B,S,H] -> spikes[B,S,H]   (B=8, S=2048, H=4096, fp32)
//   mem = decay*mem + x_t ; ref = max(ref-1,0)
//   spk = (ref==0 && mem>thr) ; mem *= (1-spk) ; ref += 5*spk
//
// R12 (float4, 8192 thr) = 95.0us: wide accesses fixed the LSU cost but
// occ 2.7% / issue 54.5% showed the stream is now concentrated on too few
// warps (per-warp issue floor ~42us) with no latency hiding. R13: float2
// lanes, 16384 threads, 512 single-warp blocks -> 3.46 warps/SM. Per-warp
// issue floor ~21us, 2x latency hiding, LSU cost/unit 0.215 (still far
// below the DRAM floor). 8-stage cp.async pipeline, 32KB smem/block,
// ~12.6MB chip-wide in flight.

#define LIF_B 8
#define LIF_S 2048
#define LIF_H 4096

static constexpr int U = 16;               // timesteps per stage
static constexpr int STAGES = 8;           // 8 * 16*64*4B = 32KB smem/block
static constexpr int NCHUNK = LIF_S / U;   // 128
static constexpr float REFRACTORY = 5.0f;

__global__ __launch_bounds__(32, 4)
void lif_scan_v2(const float* __restrict__ x,
                 const float* __restrict__ thr_p,
                 const float* __restrict__ dec_p,
                 float* __restrict__ out)
{
    __shared__ float smem[STAGES][U][64];    // per-stage tile: 16 t x 64 neurons

    const int lane = threadIdx.x;            // 0..31
    const int n0   = blockIdx.x * 64;        // first neuron of this block
    const int b     = n0 >> 12;              // n0 / H  (64 divides 4096: no straddle)
    const int hbase = n0 & (LIF_H - 1);      // n0 % H

    const float thr   = __ldg(thr_p);
    const float decay = __ldg(dec_p);

    const float* __restrict__ xbase = x   + b * (LIF_S * LIF_H) + hbase;
    float* __restrict__       obase = out + b * (LIF_S * LIF_H) + hbase + lane * 2;

    // Copy role: tile row = 64 floats = 256B, covered by 16 lanes (16B each).
    // lane -> (row parity rhalf = lane>>4, 16B column c16 = lane&15);
    // copies rows rhalf + 2j, j = 0..7  -> 8x cp.async per chunk per thread.
    const int rhalf = lane >> 4;             // 0..1
    const int c16   = lane & 15;             // 0..15
    const float* __restrict__ wsrc = xbase + rhalf * LIF_H + c16 * 4;
    const unsigned smem0 =
        (unsigned)__cvta_generic_to_shared(&smem[0][rhalf][c16 * 4]);

    auto issue_chunk = [&](int c) {
        const unsigned sbase = smem0 + (unsigned)(c % STAGES) * (U * 256u);
        const float* src = wsrc + (c * U) * LIF_H;
        #pragma unroll
        for (int j = 0; j < 8; ++j) {
            asm volatile("cp.async.cg.shared.global [%0], [%1], 16;\n"
                         :: "r"(sbase + (unsigned)j * 2u * 256u),
                            "l"(src + j * 2 * LIF_H));
        }
    };

    // Prologue: fill STAGES-2 stages, one commit group each.
    #pragma unroll
    for (int c = 0; c < STAGES - 2; ++c) {
        issue_chunk(c);
        asm volatile("cp.async.commit_group;\n" ::: "memory");
    }

    // 2 independent neuron states per thread (h, h+1).
    float mem0 = 0.f, mem1 = 0.f;
    float ref0 = 0.f, ref1 = 0.f;

    for (int c = 0; c < NCHUNK; ++c) {
        if (c + STAGES - 2 < NCHUNK)
            issue_chunk(c + STAGES - 2);
        // Always commit (empty tail groups keep wait_group<STAGES-2> aligned
        // so chunk c's group is guaranteed complete below).
        asm volatile("cp.async.commit_group;\n" ::: "memory");
        asm volatile("cp.async.wait_group %0;\n" :: "n"(STAGES - 2) : "memory");
        __syncwarp();   // single-warp block: producer == consumer warp

        const int s = c % STAGES;

        // Batch 16 LDS.64 (32 lanes x 8B = two conflict-free 128B phases).
        float2 v[U];
        #pragma unroll
        for (int i = 0; i < U; ++i)
            v[i] = *reinterpret_cast<const float2*>(&smem[s][i][lane * 2]);

        float* __restrict__ o = obase + (c * U) * LIF_H;
        #pragma unroll
        for (int i = 0; i < U; ++i) {
            float2 spk;

            mem0 = fmaf(decay, mem0, v[i].x);
            ref0 = fmaxf(ref0 - 1.0f, 0.0f);
            {
                const bool sp = (ref0 == 0.0f) && (mem0 > thr);
                spk.x = sp ? 1.0f : 0.0f;
                mem0  = sp ? 0.0f : mem0;
                ref0  = sp ? REFRACTORY : ref0;   // spike implies ref was 0
            }
            mem1 = fmaf(decay, mem1, v[i].y);
            ref1 = fmaxf(ref1 - 1.0f, 0.0f);
            {
                const bool sp = (ref1 == 0.0f) && (mem1 > thr);
                spk.y = sp ? 1.0f : 0.0f;
                mem1  = sp ? 0.0f : mem1;
                ref1  = sp ? REFRACTORY : ref1;
            }

            *reinterpret_cast<float2*>(&o[i * LIF_H]) = spk;   // STG.64
        }
    }
}

extern "C" void kernel_launch(void* const* d_in, const int* in_sizes, int n_in,
                              void* d_out, int out_size)
{
    // metadata order: x [B,S,H] f32, membrane_threshold f32, decay_rate f32
    const float* x     = (const float*)d_in[0];
    const float* thr_p = (const float*)d_in[1];
    const float* dec_p = (const float*)d_in[2];
    float* out = (float*)d_out;

    const int blocks = (LIF_B * LIF_H) / 64;   // 512 blocks, exact cover

    lif_scan_v2<<<blocks, 32>>>(x, thr_p, dec_p, out);
}